// round 6
// baseline (speedup 1.0000x reference)
#include <cuda_runtime.h>
#include <cstdint>

#define BATCH   32
#define LPTS    8192
#define MSEL    2048
#define NTHR    1024
#define PPT     (LPTS / NTHR)   // 8 points per thread

// Selected indices, written by fps kernel, read by gather kernel.
__device__ int g_fps_idx[BATCH * MSEL];

// ---------------------------------------------------------------------------
// FPS kernel: one CTA per batch. Candidate coords + running min-dist live in
// registers (8 pts/thread). Two __syncthreads per iteration:
//   compute+warp-reduce -> smem -> warp0 final reduce -> publish last point.
// Distance numerics match LLVM's contracted lowering of the XLA reduce
// BITWISE:  d = fma(dz,dz, fma(dx,dx, fl(dy*dy)))
// (InstCombine folds the +0 init into dx*dx; DAGCombiner fuses operand-0
//  fmuls first, leaving dy*dy as the separately-rounded term.)
// Argmax tie-break: first occurrence (lowest index), matching jnp.argmax.
// ---------------------------------------------------------------------------
__global__ void __launch_bounds__(NTHR, 1)
fps_kernel(const float* __restrict__ coords)
{
    __shared__ float s_red_v[32];
    __shared__ int   s_red_i[32];
    __shared__ float s_last[3];

    const int b    = blockIdx.x;
    const int t    = threadIdx.x;
    const int lane = t & 31;
    const int wid  = t >> 5;
    const float* __restrict__ cb = coords + (size_t)b * LPTS * 3;

    // Load this thread's 8 candidate points into registers (also warms L1
    // with the whole 96KB coords slab for the per-iteration lane0 refetch).
    float cx[PPT], cy[PPT], cz[PPT], md[PPT];
#pragma unroll
    for (int k = 0; k < PPT; k++) {
        const int p = t + k * NTHR;
        cx[k] = cb[p * 3 + 0];
        cy[k] = cb[p * 3 + 1];
        cz[k] = cb[p * 3 + 2];
        md[k] = __int_as_float(0x7f800000);   // +inf
    }
    if (t == 0) {
        g_fps_idx[b * MSEL] = 0;              // deterministic start at point 0
        s_last[0] = cb[0];
        s_last[1] = cb[1];
        s_last[2] = cb[2];
    }
    __syncthreads();

    for (int it = 1; it < MSEL; it++) {
        const float lx = s_last[0];
        const float ly = s_last[1];
        const float lz = s_last[2];

        float bv = -1.0f;           // distances are >= 0
        int   bi = 0x7fffffff;

#pragma unroll
        for (int k = 0; k < PPT; k++) {
            const float dx = cx[k] - lx;
            const float dy = cy[k] - ly;
            const float dz = cz[k] - lz;
            // d = fma(dz,dz, fma(dx,dx, dy*dy))  -- exact reference rounding
            float d = __fmul_rn(dy, dy);
            d = __fmaf_rn(dx, dx, d);
            d = __fmaf_rn(dz, dz, d);
            const float m = fminf(md[k], d);
            md[k] = m;
            // k ascending => global index t + k*1024 ascending: strict '>'
            // keeps the first (lowest-index) occurrence among local ties.
            if (m > bv) { bv = m; bi = t + (k << 10); }
        }

        // Warp-level argmax reduce; tie -> lower index (matches jnp.argmax).
#pragma unroll
        for (int o = 16; o > 0; o >>= 1) {
            const float ov = __shfl_xor_sync(0xffffffffu, bv, o);
            const int   oi = __shfl_xor_sync(0xffffffffu, bi, o);
            if (ov > bv || (ov == bv && oi < bi)) { bv = ov; bi = oi; }
        }
        if (lane == 0) { s_red_v[wid] = bv; s_red_i[wid] = bi; }
        __syncthreads();

        if (wid == 0) {
            bv = s_red_v[lane];
            bi = s_red_i[lane];
#pragma unroll
            for (int o = 16; o > 0; o >>= 1) {
                const float ov = __shfl_xor_sync(0xffffffffu, bv, o);
                const int   oi = __shfl_xor_sync(0xffffffffu, bi, o);
                if (ov > bv || (ov == bv && oi < bi)) { bv = ov; bi = oi; }
            }
            if (lane == 0) {
                g_fps_idx[b * MSEL + it] = bi;
                const float* p = cb + (size_t)bi * 3;   // L1 hit (~39 cyc)
                s_last[0] = p[0];
                s_last[1] = p[1];
                s_last[2] = p[2];
            }
        }
        __syncthreads();
    }
}

// ---------------------------------------------------------------------------
// Gather kernel: full-grid float4 copy of selected features + coords.
// d_out layout: coords_out [32*2048*3] floats, then feats_out [32*2048*128].
// ---------------------------------------------------------------------------
__global__ void gather_kernel(const float* __restrict__ coords,
                              const float* __restrict__ feats,
                              float* __restrict__ out)
{
    const int gid = blockIdx.x * blockDim.x + threadIdx.x;  // 32*2048*32
    const int row = gid >> 5;          // 0 .. 65535
    const int q   = gid & 31;          // float4 index within 128-float row
    const int b   = row >> 11;
    const int src = g_fps_idx[row];

    const float4* __restrict__ f =
        (const float4*)(feats + ((size_t)b * LPTS + src) * 128);
    float4* __restrict__ o =
        (float4*)(out + (size_t)BATCH * MSEL * 3 + (size_t)row * 128);
    o[q] = f[q];

    if (q == 0) {
        const float* c = coords + ((size_t)b * LPTS + src) * 3;
        float* oc = out + (size_t)row * 3;
        oc[0] = c[0];
        oc[1] = c[1];
        oc[2] = c[2];
    }
}

extern "C" void kernel_launch(void* const* d_in, const int* in_sizes, int n_in,
                              void* d_out, int out_size)
{
    const float* coords = (const float*)d_in[0];   // [32, 8192, 3]
    const float* feats  = (const float*)d_in[1];   // [32, 8192, 128]
    float* out = (float*)d_out;

    fps_kernel<<<BATCH, NTHR>>>(coords);

    const int total = BATCH * MSEL * 32;           // one thread per float4
    gather_kernel<<<total / 256, 256>>>(coords, feats, out);
}

// round 7
// speedup vs baseline: 1.9495x; 1.9495x over previous
#include <cuda_runtime.h>
#include <cstdint>

#define BATCH   32
#define LPTS    8192
#define MSEL    2048
#define NTHR    512
#define PPT     (LPTS / NTHR)   // 16 points per thread
#define NPAIR   (PPT / 2)       // 8 packed f32x2 pairs

typedef unsigned long long ull;

// Selected indices, written by fps kernel, read by gather kernel.
__device__ int g_fps_idx[BATCH * MSEL];

// ---- Blackwell packed f32x2 helpers (each lane rounds rn, identical to scalar)
__device__ __forceinline__ ull pk2(float lo, float hi) {
    ull r; asm("mov.b64 %0, {%1,%2};" : "=l"(r) : "f"(lo), "f"(hi)); return r;
}
__device__ __forceinline__ void upk2(ull v, float& lo, float& hi) {
    asm("mov.b64 {%0,%1}, %2;" : "=f"(lo), "=f"(hi) : "l"(v));
}
__device__ __forceinline__ ull add2(ull a, ull b) {
    ull r; asm("add.rn.f32x2 %0, %1, %2;" : "=l"(r) : "l"(a), "l"(b)); return r;
}
__device__ __forceinline__ ull mul2(ull a, ull b) {
    ull r; asm("mul.rn.f32x2 %0, %1, %2;" : "=l"(r) : "l"(a), "l"(b)); return r;
}
__device__ __forceinline__ ull fma2(ull a, ull b, ull c) {
    ull r; asm("fma.rn.f32x2 %0, %1, %2, %3;" : "=l"(r) : "l"(a), "l"(b), "l"(c)); return r;
}

// ---------------------------------------------------------------------------
// FPS kernel: one CTA per batch, 512 threads, 16 candidate points per thread
// held in packed f32x2 registers. ONE __syncthreads per iteration:
//   packed distance update -> REDUX warp argmax -> smem (double-buffered)
//   -> barrier -> every warp redundantly REDUX-reduces the 16 warp results
//   and loads the new farthest point itself (uniform-address L1 hit).
// Distance numerics are BITWISE identical to the reference lowering:
//   d = fma(dz,dz, fma(dx,dx, fl(dy*dy))),  dx = c + (-l)  (== c - l exactly)
// Argmax tie-break = first occurrence (lowest index):
//   in-thread: ascending index order + strict '>'
//   cross-lane/warp: REDUX max on distance bits (>=0, order-isomorphic),
//   then REDUX min on index among max-holders.
// ---------------------------------------------------------------------------
__global__ void __launch_bounds__(NTHR, 1)
fps_kernel(const float* __restrict__ coords)
{
    __shared__ unsigned s_v[2][16];
    __shared__ unsigned s_i[2][16];

    const int b    = blockIdx.x;
    const int t    = threadIdx.x;
    const int lane = t & 31;
    const int wid  = t >> 5;
    const float* __restrict__ cb = coords + (size_t)b * LPTS * 3;

    // Load candidate coords into packed registers (pair = indices p, p+NTHR).
    // Also warms L1 with the whole 96KB coords slab for the refetch below.
    ull cx[NPAIR], cy[NPAIR], cz[NPAIR];
    float md[PPT];
#pragma unroll
    for (int q = 0; q < NPAIR; q++) {
        const int p0 = t + (2 * q) * NTHR;
        const int p1 = p0 + NTHR;
        cx[q] = pk2(cb[p0 * 3 + 0], cb[p1 * 3 + 0]);
        cy[q] = pk2(cb[p0 * 3 + 1], cb[p1 * 3 + 1]);
        cz[q] = pk2(cb[p0 * 3 + 2], cb[p1 * 3 + 2]);
        md[2 * q]     = __int_as_float(0x7f800000);
        md[2 * q + 1] = __int_as_float(0x7f800000);
    }
    if (t == 0) g_fps_idx[b * MSEL] = 0;    // deterministic start at point 0

    // Every thread knows the first selected point directly.
    float lx = cb[0], ly = cb[1], lz = cb[2];

    for (int it = 1; it < MSEL; it++) {
        const ull nlx = pk2(-lx, -lx);
        const ull nly = pk2(-ly, -ly);
        const ull nlz = pk2(-lz, -lz);

        float    bv = -1.0f;                // distances are >= 0
        unsigned bi = 0xffffffffu;

#pragma unroll
        for (int q = 0; q < NPAIR; q++) {
            const ull dx = add2(cx[q], nlx);    // c + (-l) == c - l exactly
            const ull dy = add2(cy[q], nly);
            const ull dz = add2(cz[q], nlz);
            ull dd = mul2(dy, dy);              // fl(dy*dy) rounded alone
            dd = fma2(dx, dx, dd);
            dd = fma2(dz, dz, dd);
            float d0, d1; upk2(dd, d0, d1);
            const float m0 = fminf(md[2 * q],     d0);
            const float m1 = fminf(md[2 * q + 1], d1);
            md[2 * q]     = m0;
            md[2 * q + 1] = m1;
            // ascending global index + strict '>' => lowest index on ties
            if (m0 > bv) { bv = m0; bi = t + (2 * q) * NTHR; }
            if (m1 > bv) { bv = m1; bi = t + (2 * q) * NTHR + NTHR; }
        }

        // Warp argmax via REDUX: bits of non-negative floats are monotonic.
        const unsigned vb   = __float_as_uint(bv);
        const unsigned wmax = __reduce_max_sync(0xffffffffu, vb);
        const unsigned wcnd = (vb == wmax) ? bi : 0xffffffffu;
        const unsigned wmin = __reduce_min_sync(0xffffffffu, wcnd);

        const int p = it & 1;               // double buffer: no 2nd barrier
        if (lane == 0) { s_v[p][wid] = wmax; s_i[p][wid] = wmin; }
        __syncthreads();

        // Every warp redundantly reduces the 16 warp results (lanes 16-31
        // mirror lanes 0-15 harmlessly: duplicate values can't break
        // max, and the min-index among max-holders is unchanged).
        const unsigned v    = s_v[p][lane & 15];
        const unsigned i    = s_i[p][lane & 15];
        const unsigned bmax = __reduce_max_sync(0xffffffffu, v);
        const unsigned cnd  = (v == bmax) ? i : 0xffffffffu;
        const unsigned bidx = __reduce_min_sync(0xffffffffu, cnd);

        if (t == 0) g_fps_idx[b * MSEL + it] = (int)bidx;

        // All lanes load the new farthest point: uniform address, L1 hit.
        const float* pp = cb + (size_t)bidx * 3;
        lx = pp[0]; ly = pp[1]; lz = pp[2];
    }
}

// ---------------------------------------------------------------------------
// Gather kernel: full-grid float4 copy of selected features + coords.
// d_out layout: coords_out [32*2048*3] floats, then feats_out [32*2048*128].
// ---------------------------------------------------------------------------
__global__ void gather_kernel(const float* __restrict__ coords,
                              const float* __restrict__ feats,
                              float* __restrict__ out)
{
    const int gid = blockIdx.x * blockDim.x + threadIdx.x;  // 32*2048*32
    const int row = gid >> 5;          // 0 .. 65535
    const int q   = gid & 31;          // float4 index within 128-float row
    const int b   = row >> 11;
    const int src = g_fps_idx[row];

    const float4* __restrict__ f =
        (const float4*)(feats + ((size_t)b * LPTS + src) * 128);
    float4* __restrict__ o =
        (float4*)(out + (size_t)BATCH * MSEL * 3 + (size_t)row * 128);
    o[q] = f[q];

    if (q == 0) {
        const float* c = coords + ((size_t)b * LPTS + src) * 3;
        float* oc = out + (size_t)row * 3;
        oc[0] = c[0];
        oc[1] = c[1];
        oc[2] = c[2];
    }
}

extern "C" void kernel_launch(void* const* d_in, const int* in_sizes, int n_in,
                              void* d_out, int out_size)
{
    const float* coords = (const float*)d_in[0];   // [32, 8192, 3]
    const float* feats  = (const float*)d_in[1];   // [32, 8192, 128]
    float* out = (float*)d_out;

    fps_kernel<<<BATCH, NTHR>>>(coords);

    const int total = BATCH * MSEL * 32;           // one thread per float4
    gather_kernel<<<total / 256, 256>>>(coords, feats, out);
}